// round 12
// baseline (speedup 1.0000x reference)
#include <cuda_runtime.h>
#include <cuda_fp16.h>
#include <cstdint>

// ---------------------------------------------------------------------------
// Problem constants
// ---------------------------------------------------------------------------
#define BATCH      2048
#define MSEQ       64
#define STATE_DIM  32
#define CONTROL_DIM 8
#define EMBED_DIM  96
#define LATENT_DIM 128
#define HIDDEN     512
#define ROWS_XNEXT (BATCH * MSEQ)            // 131072
#define ROWS_TOTAL (BATCH + ROWS_XNEXT)      // 133120
#define MTILES     (ROWS_TOTAL / 128)        // 1040

// ---------------------------------------------------------------------------
// Scratch (__device__ globals; no allocs allowed)
// ---------------------------------------------------------------------------
__device__ __half g_Xhi[(size_t)ROWS_TOTAL * 32];
__device__ __half g_Xlo[(size_t)ROWS_TOTAL * 32];
__device__ __half g_Hahi[(size_t)ROWS_TOTAL * HIDDEN];   // H1 (single) / H3 hi
__device__ __half g_Halo[(size_t)ROWS_TOTAL * HIDDEN];   // H3 lo
__device__ __half g_Hbhi[(size_t)ROWS_TOTAL * HIDDEN];   // H2 (single)
__device__ float  g_E  [(size_t)ROWS_TOTAL * EMBED_DIM];
__device__ __half g_W1thi[512 * 32],   g_W1tlo[512 * 32];    // [N][K]
__device__ __half g_W2thi[512 * 512];                        // 1-pass: hi only
__device__ __half g_W3thi[512 * 512];
__device__ __half g_Wothi[128 * 512],  g_Wotlo[128 * 512];   // padded N 96->128

// ---------------------------------------------------------------------------
// Helpers
// ---------------------------------------------------------------------------
__device__ __forceinline__ uint32_t smem_u32(const void* p) {
    uint32_t a;
    asm("{ .reg .u64 t; cvta.to.shared.u64 t, %1; cvt.u32.u64 %0, t; }"
        : "=r"(a) : "l"(p));
    return a;
}

#define CP16(dst, src) \
    asm volatile("cp.async.cg.shared.global [%0], [%1], 16;" \
                 :: "r"(dst), "l"(src))
#define CP_COMMIT() asm volatile("cp.async.commit_group;")
#define CP_WAIT(n)  asm volatile("cp.async.wait_group %0;" :: "n"(n))

__device__ __forceinline__ void ldsm4(uint32_t* d, uint32_t addr) {
    asm volatile("ldmatrix.sync.aligned.m8n8.x4.shared.b16 {%0,%1,%2,%3}, [%4];"
                 : "=r"(d[0]), "=r"(d[1]), "=r"(d[2]), "=r"(d[3]) : "r"(addr));
}
__device__ __forceinline__ void mma16816(float* c, const uint32_t* a,
                                         uint32_t b0, uint32_t b1) {
    asm volatile(
        "mma.sync.aligned.m16n8k16.row.col.f32.f16.f16.f32 "
        "{%0,%1,%2,%3}, {%4,%5,%6,%7}, {%8,%9}, {%0,%1,%2,%3};"
        : "+f"(c[0]), "+f"(c[1]), "+f"(c[2]), "+f"(c[3])
        : "r"(a[0]), "r"(a[1]), "r"(a[2]), "r"(a[3]), "r"(b0), "r"(b1));
}

__device__ __forceinline__ void split_h(float v, __half& h, __half& l) {
    h = __float2half(v);
    l = __float2half(v - __half2float(h));
}
__device__ __forceinline__ void split_pack(float v0, float v1,
                                           uint32_t& hi, uint32_t& lo) {
    __half h0, l0, h1, l1;
    split_h(v0, h0, l0);
    split_h(v1, h1, l1);
    hi = (uint32_t)__half_as_ushort(h0) | ((uint32_t)__half_as_ushort(h1) << 16);
    lo = (uint32_t)__half_as_ushort(l0) | ((uint32_t)__half_as_ushort(l1) << 16);
}
__device__ __forceinline__ uint32_t pack_h2(float a, float b) {
    __half2 h = __floats2half2_rn(a, b);
    return *reinterpret_cast<uint32_t*>(&h);
}

#define TILE_B  10240          // 128 rows * 80 bytes

// ---------------------------------------------------------------------------
// gemm_big: 1-pass fp16 GEMM for the two dominant 512x512 layers.
// Block tile 128(m) x 256(n), 8 warps (2x4), warp tile 64x64.
// Per ks16: 8 ldsm4 feed 32 MMAs (2x better smem/MMA ratio than 64x32).
// 4-stage cp.async ring, 30720B/stage, 1 block/SM.
// Loader chunk math: each row = 4 data chunks of 16B (80B padded rows);
// A tile = 128*4 = 512 chunks (2/thread), B tile = 256*4 = 1024 (4/thread).
// OUTM: 1 = single fp16 out, 2 = hi/lo split fp16 out. RELU always on.
// ---------------------------------------------------------------------------
#define BTILE_A 10240          // 128 rows * 80B
#define BTILE_Bb 20480         // 256 rows * 80B
#define BSTG    (BTILE_A + BTILE_Bb)
#define BIG_STAGES 4
#define BIG_KB  16

template<int OUTM>
__global__ __launch_bounds__(256, 1)
void gemm_big(const __half* __restrict__ A, int ldA,
              const __half* __restrict__ B, int ldB,
              const float* __restrict__ bias,
              __half* __restrict__ Chi, __half* __restrict__ Clo, int ldC)
{
    extern __shared__ __align__(128) uint8_t dsm[];
    const uint32_t sbase = smem_u32(dsm);

    const int tid  = threadIdx.x;
    const int wid  = tid >> 5;
    const int lane = tid & 31;
    const int row0 = blockIdx.y * 128;
    const int n0   = blockIdx.x * 256;

    const int m_base = (wid >> 2) * 64;   // 0 or 64
    const int n_base = (wid & 3) * 64;    // 0,64,128,192

    const uint32_t aoff = (uint32_t)(m_base + (lane & 15)) * 80 + ((lane >> 4) << 4);
    const uint32_t boff = (uint32_t)(n_base + (lane & 15)) * 80 + ((lane >> 4) << 4);

    float acc[4][8][4];
    #pragma unroll
    for (int f = 0; f < 4; f++)
        #pragma unroll
        for (int g = 0; g < 8; g++)
            #pragma unroll
            for (int e = 0; e < 4; e++)
                acc[f][g][e] = 0.f;

    auto load_kb = [&](int kb, int st) {
        const uint32_t sa = sbase + st * BSTG;
        // A tile: 128 rows x 4 chunks = 512 chunks (2 per thread)
        #pragma unroll
        for (int t = 0; t < 2; t++) {
            int q = tid + t * 256;           // 0..511
            int r = q >> 2, c = q & 3;       // r 0..127
            CP16(sa + (uint32_t)r * 80 + c * 16,
                 A + (size_t)(row0 + r) * ldA + kb * 32 + c * 8);
        }
        // B tile: 256 rows x 4 chunks = 1024 chunks (4 per thread)
        #pragma unroll
        for (int t = 0; t < 4; t++) {
            int q = tid + t * 256;           // 0..1023
            int r = q >> 2, c = q & 3;       // r 0..255
            CP16(sa + BTILE_A + (uint32_t)r * 80 + c * 16,
                 B + (size_t)(n0 + r) * ldB + kb * 32 + c * 8);
        }
    };

    auto compute_st = [&](int st) {
        const uint32_t sa = sbase + st * BSTG;
        #pragma unroll
        for (int ks = 0; ks < 2; ks++) {
            uint32_t ah[4][4], bh[4][4];
            #pragma unroll
            for (int f = 0; f < 4; f++)
                ldsm4(ah[f], sa + aoff + f * (16 * 80) + ks * 32);
            #pragma unroll
            for (int p = 0; p < 4; p++)
                ldsm4(bh[p], sa + BTILE_A + boff + p * (16 * 80) + ks * 32);
            #pragma unroll
            for (int f = 0; f < 4; f++)
                #pragma unroll
                for (int g = 0; g < 8; g++) {
                    const int p = g >> 1, s = g & 1;
                    mma16816(acc[f][g], ah[f], bh[p][s], bh[p][s + 2]);
                }
        }
    };

    // prologue: fill 3 stages
    #pragma unroll
    for (int s = 0; s < BIG_STAGES - 1; s++) {
        load_kb(s, s);
        CP_COMMIT();
    }
    // mainloop
    for (int kb = 0; kb < BIG_KB; kb++) {
        CP_WAIT(BIG_STAGES - 2);
        __syncthreads();
        const int nkb = kb + BIG_STAGES - 1;
        if (nkb < BIG_KB) load_kb(nkb, nkb % BIG_STAGES);
        CP_COMMIT();
        compute_st(kb % BIG_STAGES);
    }

    // epilogue
    #pragma unroll
    for (int f = 0; f < 4; f++) {
        const int rg = row0 + m_base + f * 16 + (lane >> 2);
        #pragma unroll
        for (int g = 0; g < 8; g++) {
            const int c = n0 + n_base + g * 8 + (lane & 3) * 2;
            const float b0 = bias[c], b1 = bias[c + 1];
            float v00 = fmaxf(acc[f][g][0] + b0, 0.f);
            float v01 = fmaxf(acc[f][g][1] + b1, 0.f);
            float v10 = fmaxf(acc[f][g][2] + b0, 0.f);
            float v11 = fmaxf(acc[f][g][3] + b1, 0.f);
            if (OUTM == 2) {
                uint32_t hi0, lo0, hi1, lo1;
                split_pack(v00, v01, hi0, lo0);
                split_pack(v10, v11, hi1, lo1);
                *(uint32_t*)(Chi + (size_t)rg * ldC + c)       = hi0;
                *(uint32_t*)(Clo + (size_t)rg * ldC + c)       = lo0;
                *(uint32_t*)(Chi + (size_t)(rg + 8) * ldC + c) = hi1;
                *(uint32_t*)(Clo + (size_t)(rg + 8) * ldC + c) = lo1;
            } else {
                *(uint32_t*)(Chi + (size_t)rg * ldC + c)       = pack_h2(v00, v01);
                *(uint32_t*)(Chi + (size_t)(rg + 8) * ldC + c) = pack_h2(v10, v11);
            }
        }
    }
}

// ---------------------------------------------------------------------------
// gemm_mma: 3-pass split kernel (proven) for L1 (K=32) and L4 (Wo).
// Block 128x128, warp tile 64x32. OUTM: 0 fp32, 1 fp16 single.
// ---------------------------------------------------------------------------
template<int KB, int STAGES, bool RELU, int OUTM>
__global__ __launch_bounds__(256, 2)
void gemm_mma(const __half* __restrict__ Ahi, const __half* __restrict__ Alo,
              int ldA,
              const __half* __restrict__ Bhi, const __half* __restrict__ Blo,
              int ldB,
              const float* __restrict__ bias,
              __half* __restrict__ Chi,
              float* __restrict__ Cf, int ldC, int Nlim)
{
    constexpr int STG = 4 * TILE_B;   // Ah, Al, Bh, Bl

    extern __shared__ __align__(128) uint8_t dsm[];
    const uint32_t sbase = smem_u32(dsm);

    const int tid  = threadIdx.x;
    const int wid  = tid >> 5;
    const int lane = tid & 31;
    const int row0 = blockIdx.y * 128;
    const int n0   = blockIdx.x * 128;

    const int m_base = (wid >> 2) * 64;
    const int n_base = (wid & 3) * 32;

    const uint32_t aoff = (uint32_t)(m_base + (lane & 15)) * 80 + ((lane >> 4) << 4);
    const uint32_t boff = (uint32_t)(n_base + (lane & 15)) * 80 + ((lane >> 4) << 4);

    float acc[4][4][4];
    #pragma unroll
    for (int f = 0; f < 4; f++)
        #pragma unroll
        for (int g = 0; g < 4; g++)
            #pragma unroll
            for (int e = 0; e < 4; e++)
                acc[f][g][e] = 0.f;

    auto load_kb = [&](int kb, int st) {
        const uint32_t sa = sbase + st * STG;
        #pragma unroll
        for (int t = 0; t < 2; t++) {
            int q = tid + t * 256;
            int r = q >> 2, c = q & 3;
            uint32_t so = (uint32_t)r * 80 + c * 16;
            size_t ga = (size_t)(row0 + r) * ldA + kb * 32 + c * 8;
            size_t gb = (size_t)(n0 + r) * ldB + kb * 32 + c * 8;
            CP16(sa + so,              Ahi + ga);
            CP16(sa + TILE_B + so,     Alo + ga);
            CP16(sa + 2 * TILE_B + so, Bhi + gb);
            CP16(sa + 3 * TILE_B + so, Blo + gb);
        }
    };

    auto compute_st = [&](int st) {
        const uint32_t sa = sbase + st * STG;
        #pragma unroll
        for (int ks = 0; ks < 2; ks++) {
            uint32_t ah[4][4], bh[2][4];
            #pragma unroll
            for (int f = 0; f < 4; f++)
                ldsm4(ah[f], sa + aoff + f * (16 * 80) + ks * 32);
            #pragma unroll
            for (int p = 0; p < 2; p++)
                ldsm4(bh[p], sa + 2 * TILE_B + boff + p * (16 * 80) + ks * 32);
            #pragma unroll
            for (int f = 0; f < 4; f++)
                #pragma unroll
                for (int g = 0; g < 4; g++) {
                    const int p = g >> 1, s = g & 1;
                    mma16816(acc[f][g], ah[f], bh[p][s], bh[p][s + 2]);
                }
            uint32_t bl[2][4];
            #pragma unroll
            for (int p = 0; p < 2; p++)
                ldsm4(bl[p], sa + 3 * TILE_B + boff + p * (16 * 80) + ks * 32);
            #pragma unroll
            for (int f = 0; f < 4; f++)
                #pragma unroll
                for (int g = 0; g < 4; g++) {
                    const int p = g >> 1, s = g & 1;
                    mma16816(acc[f][g], ah[f], bl[p][s], bl[p][s + 2]);
                }
            uint32_t al[4][4];
            #pragma unroll
            for (int f = 0; f < 4; f++)
                ldsm4(al[f], sa + TILE_B + aoff + f * (16 * 80) + ks * 32);
            #pragma unroll
            for (int f = 0; f < 4; f++)
                #pragma unroll
                for (int g = 0; g < 4; g++) {
                    const int p = g >> 1, s = g & 1;
                    mma16816(acc[f][g], al[f], bh[p][s], bh[p][s + 2]);
                }
        }
    };

    #pragma unroll
    for (int s = 0; s < STAGES - 1; s++) {
        if (s < KB) load_kb(s, s);
        CP_COMMIT();
    }
    for (int kb = 0; kb < KB; kb++) {
        CP_WAIT(STAGES - 2);
        __syncthreads();
        const int nkb = kb + STAGES - 1;
        if (nkb < KB) load_kb(nkb, nkb % STAGES);
        CP_COMMIT();
        compute_st(kb % STAGES);
    }

    #pragma unroll
    for (int f = 0; f < 4; f++) {
        const int rg = row0 + m_base + f * 16 + (lane >> 2);
        #pragma unroll
        for (int g = 0; g < 4; g++) {
            const int c = n0 + n_base + g * 8 + (lane & 3) * 2;
            if (c < Nlim) {
                const float b0 = bias[c], b1 = bias[c + 1];
                float v00 = acc[f][g][0] + b0, v01 = acc[f][g][1] + b1;
                float v10 = acc[f][g][2] + b0, v11 = acc[f][g][3] + b1;
                if (RELU) {
                    v00 = fmaxf(v00, 0.f); v01 = fmaxf(v01, 0.f);
                    v10 = fmaxf(v10, 0.f); v11 = fmaxf(v11, 0.f);
                }
                if (OUTM == 1) {
                    *(uint32_t*)(Chi + (size_t)rg * ldC + c)       = pack_h2(v00, v01);
                    *(uint32_t*)(Chi + (size_t)(rg + 8) * ldC + c) = pack_h2(v10, v11);
                } else {
                    Cf[(size_t)rg * ldC + c]           = v00;
                    Cf[(size_t)rg * ldC + c + 1]       = v01;
                    Cf[(size_t)(rg + 8) * ldC + c]     = v10;
                    Cf[(size_t)(rg + 8) * ldC + c + 1] = v11;
                }
            }
        }
    }
}

// ---------------------------------------------------------------------------
// One merged converter launch
// ---------------------------------------------------------------------------
#define XC   (ROWS_TOTAL * 32)
#define W1C  (512 * 32)
#define W2C  (512 * 512)
#define W3C  (512 * 512)
#define WOC  (128 * 512)
#define CONVTOT (XC + W1C + W2C + W3C + WOC)

__global__ void conv_all(const float* __restrict__ xk, const float* __restrict__ xn,
                         const float* __restrict__ W1, const float* __restrict__ W2,
                         const float* __restrict__ W3, const float* __restrict__ Wo,
                         __half* __restrict__ Xhi, __half* __restrict__ Xlo,
                         __half* __restrict__ W1thi, __half* __restrict__ W1tlo,
                         __half* __restrict__ W2thi, __half* __restrict__ W3thi,
                         __half* __restrict__ Wothi, __half* __restrict__ Wotlo)
{
    int i = blockIdx.x * 256 + threadIdx.x;
    if (i < XC) {
        int row = i >> 5, c = i & 31;
        float v = (row < BATCH) ? xk[row * 32 + c]
                                : xn[(size_t)(row - BATCH) * 32 + c];
        __half h, l; split_h(v, h, l);
        size_t o = (size_t)row * 32 + c;
        Xhi[o] = h; Xlo[o] = l;
        return;
    }
    i -= XC;
    if (i < W1C) {
        int k = i / 512, n = i % 512;
        __half h, l; split_h(W1[k * 512 + n], h, l);
        W1thi[n * 32 + k] = h; W1tlo[n * 32 + k] = l;
        return;
    }
    i -= W1C;
    if (i < W2C) {
        int k = i / 512, n = i % 512;
        W2thi[(size_t)n * 512 + k] = __float2half(W2[(size_t)k * 512 + n]);
        return;
    }
    i -= W2C;
    if (i < W3C) {
        int k = i / 512, n = i % 512;
        W3thi[(size_t)n * 512 + k] = __float2half(W3[(size_t)k * 512 + n]);
        return;
    }
    i -= W3C;
    {
        int k = i / 128, n = i % 128;
        float v = (n < 96) ? Wo[(size_t)k * 96 + n] : 0.f;
        __half h, l; split_h(v, h, l);
        Wothi[(size_t)n * 512 + k] = h; Wotlo[(size_t)n * 512 + k] = l;
    }
}

// ---------------------------------------------------------------------------
// z_target assembly + scan (unchanged, fp32-exact)
// ---------------------------------------------------------------------------
__device__ __forceinline__ float2 ffma2(float a, float2 b, float2 c) {
    float2 aa = make_float2(a, a);
    unsigned long long A = *reinterpret_cast<unsigned long long*>(&aa);
    unsigned long long B = *reinterpret_cast<unsigned long long*>(&b);
    unsigned long long C = *reinterpret_cast<unsigned long long*>(&c);
    asm("fma.rn.f32x2 %0, %1, %2, %0;" : "+l"(C) : "l"(A), "l"(B));
    return *reinterpret_cast<float2*>(&C);
}

__global__ void ztarget_kernel(const float* __restrict__ x_next,
                               const float* __restrict__ E_xnext,
                               float* __restrict__ zt)
{
    const size_t idx = (size_t)blockIdx.x * blockDim.x + threadIdx.x;
    const size_t total = (size_t)ROWS_XNEXT * (LATENT_DIM / 4);
    if (idx >= total) return;
    const size_t r = idx >> 5;
    const int    q = (int)(idx & 31);
    float4 v;
    if (q < STATE_DIM / 4)
        v = ((const float4*)x_next)[r * (STATE_DIM / 4) + q];
    else
        v = ((const float4*)E_xnext)[r * (EMBED_DIM / 4) + (q - STATE_DIM / 4)];
    ((float4*)zt)[r * (LATENT_DIM / 4) + q] = v;
}

#define SCAN_ROWS 8
__global__ __launch_bounds__(256)
void scan_kernel(const float* __restrict__ x_k, const float* __restrict__ u_seq,
                 const float* __restrict__ Amat, const float* __restrict__ Bmat,
                 const float* __restrict__ E,
                 float* __restrict__ z_pred, float* __restrict__ x_pred)
{
    __shared__ float zsh[SCAN_ROWS][LATENT_DIM];
    __shared__ float ush[SCAN_ROWS][CONTROL_DIM];

    const int tid = threadIdx.x;
    const int lr  = tid >> 5;
    const int j   = tid & 31;
    const int b   = blockIdx.x * SCAN_ROWS + lr;
    const int d0  = j * 4;

    float4 z;
    if (d0 < STATE_DIM) z = *(const float4*)(x_k + (size_t)b * STATE_DIM + d0);
    else                z = *(const float4*)(E   + (size_t)b * EMBED_DIM + (d0 - STATE_DIM));
    zsh[lr][d0 + 0] = z.x; zsh[lr][d0 + 1] = z.y;
    zsh[lr][d0 + 2] = z.z; zsh[lr][d0 + 3] = z.w;
    if (j < CONTROL_DIM)
        ush[lr][j] = u_seq[((size_t)b * MSEQ + 0) * CONTROL_DIM + j];
    __syncwarp();

    for (int i = 0; i < MSEQ; i++) {
        float2 acc01 = make_float2(0.f, 0.f);
        float2 acc23 = make_float2(0.f, 0.f);

        #pragma unroll
        for (int c = 0; c < CONTROL_DIM; c++) {
            const float uc = ush[lr][c];
            float4 brow = *(const float4*)(Bmat + (size_t)c * LATENT_DIM + d0);
            acc01 = ffma2(uc, make_float2(brow.x, brow.y), acc01);
            acc23 = ffma2(uc, make_float2(brow.z, brow.w), acc23);
        }
        #pragma unroll 32
        for (int k = 0; k < LATENT_DIM; k++) {
            const float zk = zsh[lr][k];
            float4 arow = *(const float4*)(Amat + (size_t)k * LATENT_DIM + d0);
            acc01 = ffma2(zk, make_float2(arow.x, arow.y), acc01);
            acc23 = ffma2(zk, make_float2(arow.z, arow.w), acc23);
        }
        __syncwarp();

        zsh[lr][d0 + 0] = acc01.x; zsh[lr][d0 + 1] = acc01.y;
        zsh[lr][d0 + 2] = acc23.x; zsh[lr][d0 + 3] = acc23.y;
        if (j < CONTROL_DIM && i + 1 < MSEQ)
            ush[lr][j] = u_seq[((size_t)b * MSEQ + (i + 1)) * CONTROL_DIM + j];

        const size_t orow = (size_t)b * MSEQ + i;
        float4 out = make_float4(acc01.x, acc01.y, acc23.x, acc23.y);
        *(float4*)(z_pred + orow * LATENT_DIM + d0) = out;
        if (d0 < STATE_DIM)
            *(float4*)(x_pred + orow * STATE_DIM + d0) = out;
        __syncwarp();
    }
}

// ---------------------------------------------------------------------------
// kernel_launch
// Inputs: 0:x_k 1:u_seq 2:x_next_seq 3:W1 4:b1 5:W2 6:b2 7:W3 8:b3
//         9:Wo 10:bo 11:A 12:Bmat
// ---------------------------------------------------------------------------
extern "C" void kernel_launch(void* const* d_in, const int* in_sizes, int n_in,
                              void* d_out, int out_size)
{
    const float* x_k    = (const float*)d_in[0];
    const float* u_seq  = (const float*)d_in[1];
    const float* x_next = (const float*)d_in[2];
    const float* W1     = (const float*)d_in[3];
    const float* b1     = (const float*)d_in[4];
    const float* W2     = (const float*)d_in[5];
    const float* b2     = (const float*)d_in[6];
    const float* W3     = (const float*)d_in[7];
    const float* b3     = (const float*)d_in[8];
    const float* Wo     = (const float*)d_in[9];
    const float* bo     = (const float*)d_in[10];
    const float* Amat   = (const float*)d_in[11];
    const float* Bmat   = (const float*)d_in[12];

    float* out      = (float*)d_out;
    float* z_pred   = out;
    float* x_pred   = out + (size_t)BATCH * MSEQ * LATENT_DIM;
    float* z_target = x_pred + (size_t)BATCH * MSEQ * STATE_DIM;

    __half *Xhi, *Xlo, *Hahi, *Halo, *Hbhi;
    __half *W1thi, *W1tlo, *W2thi, *W3thi, *Wothi, *Wotlo;
    float* E;
    cudaGetSymbolAddress((void**)&Xhi,  g_Xhi);  cudaGetSymbolAddress((void**)&Xlo,  g_Xlo);
    cudaGetSymbolAddress((void**)&Hahi, g_Hahi); cudaGetSymbolAddress((void**)&Halo, g_Halo);
    cudaGetSymbolAddress((void**)&Hbhi, g_Hbhi);
    cudaGetSymbolAddress((void**)&W1thi, g_W1thi); cudaGetSymbolAddress((void**)&W1tlo, g_W1tlo);
    cudaGetSymbolAddress((void**)&W2thi, g_W2thi);
    cudaGetSymbolAddress((void**)&W3thi, g_W3thi);
    cudaGetSymbolAddress((void**)&Wothi, g_Wothi); cudaGetSymbolAddress((void**)&Wotlo, g_Wotlo);
    cudaGetSymbolAddress((void**)&E, g_E);

    const int SMEM_P3  = 2 * 4 * TILE_B;       // 81920 (3-pass, 2 stages)
    const int SMEM_BIG = BIG_STAGES * BSTG;    // 122880
    cudaFuncSetAttribute(gemm_mma<1,  2, true,  1>,
                         cudaFuncAttributeMaxDynamicSharedMemorySize, SMEM_P3);
    cudaFuncSetAttribute(gemm_big<1>,
                         cudaFuncAttributeMaxDynamicSharedMemorySize, SMEM_BIG);
    cudaFuncSetAttribute(gemm_big<2>,
                         cudaFuncAttributeMaxDynamicSharedMemorySize, SMEM_BIG);
    cudaFuncSetAttribute(gemm_mma<16, 2, false, 0>,
                         cudaFuncAttributeMaxDynamicSharedMemorySize, SMEM_P3);

    // all conversions in one launch                            (launch 1)
    conv_all<<<(CONVTOT + 255) / 256, 256>>>(
        x_k, x_next, W1, W2, W3, Wo,
        Xhi, Xlo, W1thi, W1tlo, W2thi, W3thi, Wothi, Wotlo);

    // L1: 3-pass (K=32), single-fp16 out -> Hahi              (launch 2)
    gemm_mma<1, 2, true, 1><<<dim3(4, MTILES), 256, SMEM_P3>>>(
        Xhi, Xlo, 32, W1thi, W1tlo, 32, b1, Hahi, nullptr, 512, 512);
    // L2: 1-pass big-tile, single out -> Hbhi                 (launch 3)
    gemm_big<1><<<dim3(2, MTILES), 256, SMEM_BIG>>>(
        Hahi, 512, W2thi, 512, b2, Hbhi, nullptr, 512);
    // L3: 1-pass big-tile, split out -> Hahi/Halo             (launch 4)
    gemm_big<2><<<dim3(2, MTILES), 256, SMEM_BIG>>>(
        Hbhi, 512, W3thi, 512, b3, Hahi, Halo, 512);
    // L4: 3-pass, fp32 out -> E                               (launch 5)
    gemm_mma<16, 2, false, 0><<<dim3(1, MTILES), 256, SMEM_P3>>>(
        Hahi, Halo, 512, Wothi, Wotlo, 512, bo, nullptr, E, 96, 96);

    // outputs                                                 (launches 6,7)
    {
        const size_t total = (size_t)ROWS_XNEXT * (LATENT_DIM / 4);
        int nb = (int)((total + 255) / 256);
        ztarget_kernel<<<nb, 256>>>(x_next, E + (size_t)BATCH * EMBED_DIM, z_target);
    }
    scan_kernel<<<BATCH / SCAN_ROWS, 256>>>(x_k, u_seq, Amat, Bmat, E, z_pred, x_pred);

    (void)in_sizes; (void)n_in; (void)out_size;
}

// round 13
// speedup vs baseline: 1.8701x; 1.8701x over previous
#include <cuda_runtime.h>
#include <cuda_fp16.h>
#include <cstdint>

// ---------------------------------------------------------------------------
// Problem constants
// ---------------------------------------------------------------------------
#define BATCH      2048
#define MSEQ       64
#define STATE_DIM  32
#define CONTROL_DIM 8
#define EMBED_DIM  96
#define LATENT_DIM 128
#define HIDDEN     512
#define ROWS_XNEXT (BATCH * MSEQ)            // 131072
#define ROWS_TOTAL (BATCH + ROWS_XNEXT)      // 133120
#define MTILES     (ROWS_TOTAL / 128)        // 1040

// ---------------------------------------------------------------------------
// Scratch (__device__ globals; no allocs allowed)
// ---------------------------------------------------------------------------
__device__ __half g_Xhi[(size_t)ROWS_TOTAL * 32];
__device__ __half g_Xlo[(size_t)ROWS_TOTAL * 32];
__device__ __half g_Hahi[(size_t)ROWS_TOTAL * HIDDEN];   // H1 / H3 (single fp16)
__device__ __half g_Hbhi[(size_t)ROWS_TOTAL * HIDDEN];   // H2 (single fp16)
__device__ float  g_E  [(size_t)ROWS_TOTAL * EMBED_DIM];
__device__ __half g_W1thi[512 * 32],  g_W1tlo[512 * 32];  // [N][K]
__device__ __half g_W2thi[512 * 512];                     // 1-pass: hi only
__device__ __half g_W3thi[512 * 512];
__device__ __half g_Wothi[128 * 512];                     // padded N 96->128, hi only

// ---------------------------------------------------------------------------
// Helpers
// ---------------------------------------------------------------------------
__device__ __forceinline__ uint32_t smem_u32(const void* p) {
    uint32_t a;
    asm("{ .reg .u64 t; cvta.to.shared.u64 t, %1; cvt.u32.u64 %0, t; }"
        : "=r"(a) : "l"(p));
    return a;
}

#define CP16(dst, src) \
    asm volatile("cp.async.cg.shared.global [%0], [%1], 16;" \
                 :: "r"(dst), "l"(src))
#define CP_COMMIT() asm volatile("cp.async.commit_group;")
#define CP_WAIT(n)  asm volatile("cp.async.wait_group %0;" :: "n"(n))

__device__ __forceinline__ void ldsm4(uint32_t* d, uint32_t addr) {
    asm volatile("ldmatrix.sync.aligned.m8n8.x4.shared.b16 {%0,%1,%2,%3}, [%4];"
                 : "=r"(d[0]), "=r"(d[1]), "=r"(d[2]), "=r"(d[3]) : "r"(addr));
}
__device__ __forceinline__ void mma16816(float* c, const uint32_t* a,
                                         uint32_t b0, uint32_t b1) {
    asm volatile(
        "mma.sync.aligned.m16n8k16.row.col.f32.f16.f16.f32 "
        "{%0,%1,%2,%3}, {%4,%5,%6,%7}, {%8,%9}, {%0,%1,%2,%3};"
        : "+f"(c[0]), "+f"(c[1]), "+f"(c[2]), "+f"(c[3])
        : "r"(a[0]), "r"(a[1]), "r"(a[2]), "r"(a[3]), "r"(b0), "r"(b1));
}

__device__ __forceinline__ void split_h(float v, __half& h, __half& l) {
    h = __float2half(v);
    l = __float2half(v - __half2float(h));
}
__device__ __forceinline__ uint32_t pack_h2(float a, float b) {
    __half2 h = __floats2half2_rn(a, b);
    return *reinterpret_cast<uint32_t*>(&h);
}

// ---------------------------------------------------------------------------
// fp16 mma.sync GEMM, NPASS-split, fp32 accumulate. (PROVEN R10 config)
// Block 128x128, 8 warps, warp tile 64x32, 2 blocks/SM.
// NPASS==3: C = Ah*Bh + Ah*Bl + Al*Bh   (near-exact)
// NPASS==1: C = Ah*Bh                   (pure fp16 operands)
// OUTM: 0 = fp32 store (N-guarded), 1 = single fp16 store
// B fragments via PLAIN (non-trans) ldmatrix, pairing (r_s, r_{s+2}).
// Pass-major MMA order. STAGES-deep cp.async ring, always-commit.
// ---------------------------------------------------------------------------
#define TILE_B  10240          // 128 rows * 80 bytes

template<int KB, int STAGES, int NPASS, bool RELU, int OUTM>
__global__ __launch_bounds__(256, 2)
void gemm_mma(const __half* __restrict__ Ahi, const __half* __restrict__ Alo,
              int ldA,
              const __half* __restrict__ Bhi, const __half* __restrict__ Blo,
              int ldB,
              const float* __restrict__ bias,
              __half* __restrict__ Chi,
              float* __restrict__ Cf, int ldC, int Nlim)
{
    constexpr int A_TILES = (NPASS == 1) ? 1 : 2;
    constexpr int B_TILES = (NPASS == 3) ? 2 : 1;
    constexpr int STG     = (A_TILES + B_TILES) * TILE_B;
    constexpr uint32_t BOFF  = A_TILES * TILE_B;            // Bh tile
    constexpr uint32_t BLOFF = (A_TILES + 1) * TILE_B;      // Bl tile (3-pass)

    extern __shared__ __align__(128) uint8_t dsm[];
    const uint32_t sbase = smem_u32(dsm);

    const int tid  = threadIdx.x;
    const int wid  = tid >> 5;
    const int lane = tid & 31;
    const int row0 = blockIdx.y * 128;
    const int n0   = blockIdx.x * 128;

    const int m_base = (wid >> 2) * 64;   // 0 or 64
    const int n_base = (wid & 3) * 32;    // 0,32,64,96

    const uint32_t aoff = (uint32_t)(m_base + (lane & 15)) * 80 + ((lane >> 4) << 4);
    const uint32_t boff = (uint32_t)(n_base + (lane & 15)) * 80 + ((lane >> 4) << 4);

    float acc[4][4][4];
    #pragma unroll
    for (int f = 0; f < 4; f++)
        #pragma unroll
        for (int g = 0; g < 4; g++)
            #pragma unroll
            for (int e = 0; e < 4; e++)
                acc[f][g][e] = 0.f;

    auto load_kb = [&](int kb, int st) {
        const uint32_t sa = sbase + st * STG;
        #pragma unroll
        for (int t = 0; t < 2; t++) {
            int q = tid + t * 256;       // 0..511
            int r = q >> 2, c = q & 3;
            uint32_t so = (uint32_t)r * 80 + c * 16;
            size_t ga = (size_t)(row0 + r) * ldA + kb * 32 + c * 8;
            size_t gb = (size_t)(n0 + r) * ldB + kb * 32 + c * 8;
            CP16(sa + so, Ahi + ga);
            if (NPASS > 1)  CP16(sa + TILE_B + so, Alo + ga);
            CP16(sa + BOFF + so, Bhi + gb);
            if (NPASS == 3) CP16(sa + BLOFF + so, Blo + gb);
        }
    };

    auto compute_st = [&](int st) {
        const uint32_t sa = sbase + st * STG;
        #pragma unroll
        for (int ks = 0; ks < 2; ks++) {
            uint32_t ah[4][4], bh[2][4];
            #pragma unroll
            for (int f = 0; f < 4; f++)
                ldsm4(ah[f], sa + aoff + f * (16 * 80) + ks * 32);
            #pragma unroll
            for (int p = 0; p < 2; p++)
                ldsm4(bh[p], sa + BOFF + boff + p * (16 * 80) + ks * 32);
            // pass 1: Ah*Bh
            #pragma unroll
            for (int f = 0; f < 4; f++)
                #pragma unroll
                for (int g = 0; g < 4; g++) {
                    const int p = g >> 1, s = g & 1;
                    mma16816(acc[f][g], ah[f], bh[p][s], bh[p][s + 2]);
                }
            // pass 2 (3-pass only): Ah*Bl
            if (NPASS == 3) {
                uint32_t bl[2][4];
                #pragma unroll
                for (int p = 0; p < 2; p++)
                    ldsm4(bl[p], sa + BLOFF + boff + p * (16 * 80) + ks * 32);
                #pragma unroll
                for (int f = 0; f < 4; f++)
                    #pragma unroll
                    for (int g = 0; g < 4; g++) {
                        const int p = g >> 1, s = g & 1;
                        mma16816(acc[f][g], ah[f], bl[p][s], bl[p][s + 2]);
                    }
            }
            // final pass (NPASS>1): Al*Bh
            if (NPASS > 1) {
                uint32_t al[4][4];
                #pragma unroll
                for (int f = 0; f < 4; f++)
                    ldsm4(al[f], sa + TILE_B + aoff + f * (16 * 80) + ks * 32);
                #pragma unroll
                for (int f = 0; f < 4; f++)
                    #pragma unroll
                    for (int g = 0; g < 4; g++) {
                        const int p = g >> 1, s = g & 1;
                        mma16816(acc[f][g], al[f], bh[p][s], bh[p][s + 2]);
                    }
            }
        }
    };

    // prologue
    #pragma unroll
    for (int s = 0; s < STAGES - 1; s++) {
        if (s < KB) load_kb(s, s);
        CP_COMMIT();
    }
    // mainloop
    for (int kb = 0; kb < KB; kb++) {
        CP_WAIT(STAGES - 2);
        __syncthreads();
        const int nkb = kb + STAGES - 1;
        if (nkb < KB) load_kb(nkb, nkb % STAGES);
        CP_COMMIT();
        compute_st(kb % STAGES);
    }

    // epilogue
    #pragma unroll
    for (int f = 0; f < 4; f++) {
        const int rg = row0 + m_base + f * 16 + (lane >> 2);
        #pragma unroll
        for (int g = 0; g < 4; g++) {
            const int c = n0 + n_base + g * 8 + (lane & 3) * 2;
            if (c < Nlim) {
                const float b0 = bias[c], b1 = bias[c + 1];
                float v00 = acc[f][g][0] + b0, v01 = acc[f][g][1] + b1;
                float v10 = acc[f][g][2] + b0, v11 = acc[f][g][3] + b1;
                if (RELU) {
                    v00 = fmaxf(v00, 0.f); v01 = fmaxf(v01, 0.f);
                    v10 = fmaxf(v10, 0.f); v11 = fmaxf(v11, 0.f);
                }
                if (OUTM == 1) {
                    *(uint32_t*)(Chi + (size_t)rg * ldC + c)       = pack_h2(v00, v01);
                    *(uint32_t*)(Chi + (size_t)(rg + 8) * ldC + c) = pack_h2(v10, v11);
                } else {
                    Cf[(size_t)rg * ldC + c]           = v00;
                    Cf[(size_t)rg * ldC + c + 1]       = v01;
                    Cf[(size_t)(rg + 8) * ldC + c]     = v10;
                    Cf[(size_t)(rg + 8) * ldC + c + 1] = v11;
                }
            }
        }
    }
}

// ---------------------------------------------------------------------------
// One merged converter launch: X (hi/lo), W1 (hi/lo), W2 (hi), W3 (hi),
// Wo (hi only, N padded 96->128). Weights -> [N][K] K-major.
// ---------------------------------------------------------------------------
#define XC   (ROWS_TOTAL * 32)
#define W1C  (512 * 32)
#define W2C  (512 * 512)
#define W3C  (512 * 512)
#define WOC  (128 * 512)
#define CONVTOT (XC + W1C + W2C + W3C + WOC)

__global__ void conv_all(const float* __restrict__ xk, const float* __restrict__ xn,
                         const float* __restrict__ W1, const float* __restrict__ W2,
                         const float* __restrict__ W3, const float* __restrict__ Wo,
                         __half* __restrict__ Xhi, __half* __restrict__ Xlo,
                         __half* __restrict__ W1thi, __half* __restrict__ W1tlo,
                         __half* __restrict__ W2thi, __half* __restrict__ W3thi,
                         __half* __restrict__ Wothi)
{
    int i = blockIdx.x * 256 + threadIdx.x;
    if (i < XC) {
        int row = i >> 5, c = i & 31;
        float v = (row < BATCH) ? xk[row * 32 + c]
                                : xn[(size_t)(row - BATCH) * 32 + c];
        __half h, l; split_h(v, h, l);
        size_t o = (size_t)row * 32 + c;
        Xhi[o] = h; Xlo[o] = l;
        return;
    }
    i -= XC;
    if (i < W1C) {                       // K=32, N=512
        int k = i / 512, n = i % 512;
        __half h, l; split_h(W1[k * 512 + n], h, l);
        W1thi[n * 32 + k] = h; W1tlo[n * 32 + k] = l;
        return;
    }
    i -= W1C;
    if (i < W2C) {                       // K=512, N=512, hi only
        int k = i / 512, n = i % 512;
        W2thi[(size_t)n * 512 + k] = __float2half(W2[(size_t)k * 512 + n]);
        return;
    }
    i -= W2C;
    if (i < W3C) {
        int k = i / 512, n = i % 512;
        W3thi[(size_t)n * 512 + k] = __float2half(W3[(size_t)k * 512 + n]);
        return;
    }
    i -= W3C;
    {                                    // Wo: K=512, N=96, Npad=128, hi only
        int k = i / 128, n = i % 128;
        float v = (n < 96) ? Wo[(size_t)k * 96 + n] : 0.f;
        Wothi[(size_t)n * 512 + k] = __float2half(v);
    }
}

// ---------------------------------------------------------------------------
// z_target assembly + scan (unchanged, fp32-exact)
// ---------------------------------------------------------------------------
__device__ __forceinline__ float2 ffma2(float a, float2 b, float2 c) {
    float2 aa = make_float2(a, a);
    unsigned long long A = *reinterpret_cast<unsigned long long*>(&aa);
    unsigned long long B = *reinterpret_cast<unsigned long long*>(&b);
    unsigned long long C = *reinterpret_cast<unsigned long long*>(&c);
    asm("fma.rn.f32x2 %0, %1, %2, %0;" : "+l"(C) : "l"(A), "l"(B));
    return *reinterpret_cast<float2*>(&C);
}

__global__ void ztarget_kernel(const float* __restrict__ x_next,
                               const float* __restrict__ E_xnext,
                               float* __restrict__ zt)
{
    const size_t idx = (size_t)blockIdx.x * blockDim.x + threadIdx.x;
    const size_t total = (size_t)ROWS_XNEXT * (LATENT_DIM / 4);
    if (idx >= total) return;
    const size_t r = idx >> 5;
    const int    q = (int)(idx & 31);
    float4 v;
    if (q < STATE_DIM / 4)
        v = ((const float4*)x_next)[r * (STATE_DIM / 4) + q];
    else
        v = ((const float4*)E_xnext)[r * (EMBED_DIM / 4) + (q - STATE_DIM / 4)];
    ((float4*)zt)[r * (LATENT_DIM / 4) + q] = v;
}

#define SCAN_ROWS 8
__global__ __launch_bounds__(256)
void scan_kernel(const float* __restrict__ x_k, const float* __restrict__ u_seq,
                 const float* __restrict__ Amat, const float* __restrict__ Bmat,
                 const float* __restrict__ E,
                 float* __restrict__ z_pred, float* __restrict__ x_pred)
{
    __shared__ float zsh[SCAN_ROWS][LATENT_DIM];
    __shared__ float ush[SCAN_ROWS][CONTROL_DIM];

    const int tid = threadIdx.x;
    const int lr  = tid >> 5;
    const int j   = tid & 31;
    const int b   = blockIdx.x * SCAN_ROWS + lr;
    const int d0  = j * 4;

    float4 z;
    if (d0 < STATE_DIM) z = *(const float4*)(x_k + (size_t)b * STATE_DIM + d0);
    else                z = *(const float4*)(E   + (size_t)b * EMBED_DIM + (d0 - STATE_DIM));
    zsh[lr][d0 + 0] = z.x; zsh[lr][d0 + 1] = z.y;
    zsh[lr][d0 + 2] = z.z; zsh[lr][d0 + 3] = z.w;
    if (j < CONTROL_DIM)
        ush[lr][j] = u_seq[((size_t)b * MSEQ + 0) * CONTROL_DIM + j];
    __syncwarp();

    for (int i = 0; i < MSEQ; i++) {
        float2 acc01 = make_float2(0.f, 0.f);
        float2 acc23 = make_float2(0.f, 0.f);

        #pragma unroll
        for (int c = 0; c < CONTROL_DIM; c++) {
            const float uc = ush[lr][c];
            float4 brow = *(const float4*)(Bmat + (size_t)c * LATENT_DIM + d0);
            acc01 = ffma2(uc, make_float2(brow.x, brow.y), acc01);
            acc23 = ffma2(uc, make_float2(brow.z, brow.w), acc23);
        }
        #pragma unroll 32
        for (int k = 0; k < LATENT_DIM; k++) {
            const float zk = zsh[lr][k];
            float4 arow = *(const float4*)(Amat + (size_t)k * LATENT_DIM + d0);
            acc01 = ffma2(zk, make_float2(arow.x, arow.y), acc01);
            acc23 = ffma2(zk, make_float2(arow.z, arow.w), acc23);
        }
        __syncwarp();

        zsh[lr][d0 + 0] = acc01.x; zsh[lr][d0 + 1] = acc01.y;
        zsh[lr][d0 + 2] = acc23.x; zsh[lr][d0 + 3] = acc23.y;
        if (j < CONTROL_DIM && i + 1 < MSEQ)
            ush[lr][j] = u_seq[((size_t)b * MSEQ + (i + 1)) * CONTROL_DIM + j];

        const size_t orow = (size_t)b * MSEQ + i;
        float4 out = make_float4(acc01.x, acc01.y, acc23.x, acc23.y);
        *(float4*)(z_pred + orow * LATENT_DIM + d0) = out;
        if (d0 < STATE_DIM)
            *(float4*)(x_pred + orow * STATE_DIM + d0) = out;
        __syncwarp();
    }
}

// ---------------------------------------------------------------------------
// kernel_launch
// Inputs: 0:x_k 1:u_seq 2:x_next_seq 3:W1 4:b1 5:W2 6:b2 7:W3 8:b3
//         9:Wo 10:bo 11:A 12:Bmat
// ---------------------------------------------------------------------------
extern "C" void kernel_launch(void* const* d_in, const int* in_sizes, int n_in,
                              void* d_out, int out_size)
{
    const float* x_k    = (const float*)d_in[0];
    const float* u_seq  = (const float*)d_in[1];
    const float* x_next = (const float*)d_in[2];
    const float* W1     = (const float*)d_in[3];
    const float* b1     = (const float*)d_in[4];
    const float* W2     = (const float*)d_in[5];
    const float* b2     = (const float*)d_in[6];
    const float* W3     = (const float*)d_in[7];
    const float* b3     = (const float*)d_in[8];
    const float* Wo     = (const float*)d_in[9];
    const float* bo     = (const float*)d_in[10];
    const float* Amat   = (const float*)d_in[11];
    const float* Bmat   = (const float*)d_in[12];

    float* out      = (float*)d_out;
    float* z_pred   = out;
    float* x_pred   = out + (size_t)BATCH * MSEQ * LATENT_DIM;
    float* z_target = x_pred + (size_t)BATCH * MSEQ * STATE_DIM;

    __half *Xhi, *Xlo, *Hahi, *Hbhi;
    __half *W1thi, *W1tlo, *W2thi, *W3thi, *Wothi;
    float* E;
    cudaGetSymbolAddress((void**)&Xhi,  g_Xhi);  cudaGetSymbolAddress((void**)&Xlo,  g_Xlo);
    cudaGetSymbolAddress((void**)&Hahi, g_Hahi);
    cudaGetSymbolAddress((void**)&Hbhi, g_Hbhi);
    cudaGetSymbolAddress((void**)&W1thi, g_W1thi); cudaGetSymbolAddress((void**)&W1tlo, g_W1tlo);
    cudaGetSymbolAddress((void**)&W2thi, g_W2thi);
    cudaGetSymbolAddress((void**)&W3thi, g_W3thi);
    cudaGetSymbolAddress((void**)&Wothi, g_Wothi);
    cudaGetSymbolAddress((void**)&E, g_E);

    const int SMEM_P3 = 2 * 4 * TILE_B;   // 81920 (3-pass, 2 stages)
    const int SMEM_P1 = 4 * 2 * TILE_B;   // 81920 (1-pass, 4 stages)
    cudaFuncSetAttribute(gemm_mma<1,  2, 3, true,  1>,
                         cudaFuncAttributeMaxDynamicSharedMemorySize, SMEM_P3);
    cudaFuncSetAttribute(gemm_mma<16, 4, 1, true,  1>,
                         cudaFuncAttributeMaxDynamicSharedMemorySize, SMEM_P1);
    cudaFuncSetAttribute(gemm_mma<16, 4, 1, false, 0>,
                         cudaFuncAttributeMaxDynamicSharedMemorySize, SMEM_P1);

    // all conversions in one launch                            (launch 1)
    conv_all<<<(CONVTOT + 255) / 256, 256>>>(
        x_k, x_next, W1, W2, W3, Wo,
        Xhi, Xlo, W1thi, W1tlo, W2thi, W3thi, Wothi);

    // L1: 3-pass (K=32), single-fp16 out -> Hahi              (launch 2)
    gemm_mma<1, 2, 3, true, 1><<<dim3(4, MTILES), 256, SMEM_P3>>>(
        Xhi, Xlo, 32, W1thi, W1tlo, 32, b1, Hahi, nullptr, 512, 512);
    // L2: 1-pass fp16 -> Hbhi                                 (launch 3)
    gemm_mma<16, 4, 1, true, 1><<<dim3(4, MTILES), 256, SMEM_P1>>>(
        Hahi, nullptr, 512, W2thi, nullptr, 512, b2, Hbhi, nullptr, 512, 512);
    // L3: 1-pass fp16 -> Hahi (single, no split)              (launch 4)
    gemm_mma<16, 4, 1, true, 1><<<dim3(4, MTILES), 256, SMEM_P1>>>(
        Hbhi, nullptr, 512, W3thi, nullptr, 512, b3, Hahi, nullptr, 512, 512);
    // L4: 1-pass fp16, fp32 out -> E                          (launch 5)
    gemm_mma<16, 4, 1, false, 0><<<dim3(1, MTILES), 256, SMEM_P1>>>(
        Hahi, nullptr, 512, Wothi, nullptr, 512, bo, nullptr, E, 96, 96);

    // outputs                                                 (launches 6,7)
    {
        const size_t total = (size_t)ROWS_XNEXT * (LATENT_DIM / 4);
        int nb = (int)((total + 255) / 256);
        ztarget_kernel<<<nb, 256>>>(x_next, E + (size_t)BATCH * EMBED_DIM, z_target);
    }
    scan_kernel<<<BATCH / SCAN_ROWS, 256>>>(x_k, u_seq, Amat, Bmat, E, z_pred, x_pred);

    (void)in_sizes; (void)n_in; (void)out_size;
}

// round 14
// speedup vs baseline: 1.9225x; 1.0280x over previous
#include <cuda_runtime.h>
#include <cuda_fp16.h>
#include <cstdint>

// ---------------------------------------------------------------------------
// Problem constants
// ---------------------------------------------------------------------------
#define BATCH      2048
#define MSEQ       64
#define STATE_DIM  32
#define CONTROL_DIM 8
#define EMBED_DIM  96
#define LATENT_DIM 128
#define HIDDEN     512
#define ROWS_XNEXT (BATCH * MSEQ)            // 131072
#define ROWS_TOTAL (BATCH + ROWS_XNEXT)      // 133120
#define MTILES     (ROWS_TOTAL / 128)        // 1040

// ---------------------------------------------------------------------------
// Scratch (__device__ globals; no allocs allowed)
// ---------------------------------------------------------------------------
__device__ __half g_Xhi[(size_t)ROWS_TOTAL * 32];
__device__ __half g_Xlo[(size_t)ROWS_TOTAL * 32];
__device__ __half g_Hahi[(size_t)ROWS_TOTAL * HIDDEN];   // H1 / H3 (single fp16)
__device__ __half g_Hbhi[(size_t)ROWS_TOTAL * HIDDEN];   // H2 (single fp16)
__device__ float  g_Exk[(size_t)BATCH * EMBED_DIM];      // encoder(x_k) only
__device__ __half g_W1thi[512 * 32];                     // [N][K], hi only (2-pass)
__device__ __half g_W2thi[512 * 512];
__device__ __half g_W3thi[512 * 512];
__device__ __half g_Wothi[128 * 512];                    // padded N 96->128

// ---------------------------------------------------------------------------
// Helpers
// ---------------------------------------------------------------------------
__device__ __forceinline__ uint32_t smem_u32(const void* p) {
    uint32_t a;
    asm("{ .reg .u64 t; cvta.to.shared.u64 t, %1; cvt.u32.u64 %0, t; }"
        : "=r"(a) : "l"(p));
    return a;
}

#define CP16(dst, src) \
    asm volatile("cp.async.cg.shared.global [%0], [%1], 16;" \
                 :: "r"(dst), "l"(src))
#define CP_COMMIT() asm volatile("cp.async.commit_group;")
#define CP_WAIT(n)  asm volatile("cp.async.wait_group %0;" :: "n"(n))

__device__ __forceinline__ void ldsm4(uint32_t* d, uint32_t addr) {
    asm volatile("ldmatrix.sync.aligned.m8n8.x4.shared.b16 {%0,%1,%2,%3}, [%4];"
                 : "=r"(d[0]), "=r"(d[1]), "=r"(d[2]), "=r"(d[3]) : "r"(addr));
}
__device__ __forceinline__ void mma16816(float* c, const uint32_t* a,
                                         uint32_t b0, uint32_t b1) {
    asm volatile(
        "mma.sync.aligned.m16n8k16.row.col.f32.f16.f16.f32 "
        "{%0,%1,%2,%3}, {%4,%5,%6,%7}, {%8,%9}, {%0,%1,%2,%3};"
        : "+f"(c[0]), "+f"(c[1]), "+f"(c[2]), "+f"(c[3])
        : "r"(a[0]), "r"(a[1]), "r"(a[2]), "r"(a[3]), "r"(b0), "r"(b1));
}

__device__ __forceinline__ void split_h(float v, __half& h, __half& l) {
    h = __float2half(v);
    l = __float2half(v - __half2float(h));
}
__device__ __forceinline__ uint32_t pack_h2(float a, float b) {
    __half2 h = __floats2half2_rn(a, b);
    return *reinterpret_cast<uint32_t*>(&h);
}

// ---------------------------------------------------------------------------
// fp16 mma.sync GEMM, NPASS-split, fp32 accumulate. (PROVEN config)
// Block 128x128, 8 warps, warp tile 64x32, 2 blocks/SM.
// NPASS==2: C = (Ah+Al)*Bh   NPASS==1: C = Ah*Bh
// OUTM: 1 = single fp16 store
//       3 = fused final-layer store: rows<BATCH -> Exk[96-wide],
//           rows>=BATCH -> z_target[(r-BATCH)*128 + 32 + c] (c<96 guard)
// B fragments via PLAIN (non-trans) ldmatrix, pairing (r_s, r_{s+2}).
// Pass-major MMA order. STAGES-deep cp.async ring, always-commit.
// ---------------------------------------------------------------------------
#define TILE_B  10240          // 128 rows * 80 bytes

template<int KB, int STAGES, int NPASS, bool RELU, int OUTM>
__global__ __launch_bounds__(256, 2)
void gemm_mma(const __half* __restrict__ Ahi, const __half* __restrict__ Alo,
              int ldA,
              const __half* __restrict__ Bhi,
              int ldB,
              const float* __restrict__ bias,
              __half* __restrict__ Chi,
              float* __restrict__ Cf, float* __restrict__ Cf2,
              int ldC, int Nlim)
{
    constexpr int A_TILES = (NPASS == 1) ? 1 : 2;
    constexpr int STG     = (A_TILES + 1) * TILE_B;
    constexpr uint32_t BOFF = A_TILES * TILE_B;            // Bh tile

    extern __shared__ __align__(128) uint8_t dsm[];
    const uint32_t sbase = smem_u32(dsm);

    const int tid  = threadIdx.x;
    const int wid  = tid >> 5;
    const int lane = tid & 31;
    const int row0 = blockIdx.y * 128;
    const int n0   = blockIdx.x * 128;

    const int m_base = (wid >> 2) * 64;   // 0 or 64
    const int n_base = (wid & 3) * 32;    // 0,32,64,96

    const uint32_t aoff = (uint32_t)(m_base + (lane & 15)) * 80 + ((lane >> 4) << 4);
    const uint32_t boff = (uint32_t)(n_base + (lane & 15)) * 80 + ((lane >> 4) << 4);

    float acc[4][4][4];
    #pragma unroll
    for (int f = 0; f < 4; f++)
        #pragma unroll
        for (int g = 0; g < 4; g++)
            #pragma unroll
            for (int e = 0; e < 4; e++)
                acc[f][g][e] = 0.f;

    auto load_kb = [&](int kb, int st) {
        const uint32_t sa = sbase + st * STG;
        #pragma unroll
        for (int t = 0; t < 2; t++) {
            int q = tid + t * 256;       // 0..511
            int r = q >> 2, c = q & 3;
            uint32_t so = (uint32_t)r * 80 + c * 16;
            size_t ga = (size_t)(row0 + r) * ldA + kb * 32 + c * 8;
            size_t gb = (size_t)(n0 + r) * ldB + kb * 32 + c * 8;
            CP16(sa + so, Ahi + ga);
            if (NPASS > 1) CP16(sa + TILE_B + so, Alo + ga);
            CP16(sa + BOFF + so, Bhi + gb);
        }
    };

    auto compute_st = [&](int st) {
        const uint32_t sa = sbase + st * STG;
        #pragma unroll
        for (int ks = 0; ks < 2; ks++) {
            uint32_t ah[4][4], bh[2][4];
            #pragma unroll
            for (int f = 0; f < 4; f++)
                ldsm4(ah[f], sa + aoff + f * (16 * 80) + ks * 32);
            #pragma unroll
            for (int p = 0; p < 2; p++)
                ldsm4(bh[p], sa + BOFF + boff + p * (16 * 80) + ks * 32);
            // pass 1: Ah*Bh
            #pragma unroll
            for (int f = 0; f < 4; f++)
                #pragma unroll
                for (int g = 0; g < 4; g++) {
                    const int p = g >> 1, s = g & 1;
                    mma16816(acc[f][g], ah[f], bh[p][s], bh[p][s + 2]);
                }
            // pass 2 (NPASS>1): Al*Bh
            if (NPASS > 1) {
                uint32_t al[4][4];
                #pragma unroll
                for (int f = 0; f < 4; f++)
                    ldsm4(al[f], sa + TILE_B + aoff + f * (16 * 80) + ks * 32);
                #pragma unroll
                for (int f = 0; f < 4; f++)
                    #pragma unroll
                    for (int g = 0; g < 4; g++) {
                        const int p = g >> 1, s = g & 1;
                        mma16816(acc[f][g], al[f], bh[p][s], bh[p][s + 2]);
                    }
            }
        }
    };

    // prologue
    #pragma unroll
    for (int s = 0; s < STAGES - 1; s++) {
        if (s < KB) load_kb(s, s);
        CP_COMMIT();
    }
    // mainloop
    for (int kb = 0; kb < KB; kb++) {
        CP_WAIT(STAGES - 2);
        __syncthreads();
        const int nkb = kb + STAGES - 1;
        if (nkb < KB) load_kb(nkb, nkb % STAGES);
        CP_COMMIT();
        compute_st(kb % STAGES);
    }

    // epilogue
    #pragma unroll
    for (int f = 0; f < 4; f++) {
        const int rg0 = row0 + m_base + f * 16 + (lane >> 2);
        #pragma unroll
        for (int g = 0; g < 4; g++) {
            const int c = n0 + n_base + g * 8 + (lane & 3) * 2;
            if (c < Nlim) {
                const float b0 = bias[c], b1 = bias[c + 1];
                float v00 = acc[f][g][0] + b0, v01 = acc[f][g][1] + b1;
                float v10 = acc[f][g][2] + b0, v11 = acc[f][g][3] + b1;
                if (RELU) {
                    v00 = fmaxf(v00, 0.f); v01 = fmaxf(v01, 0.f);
                    v10 = fmaxf(v10, 0.f); v11 = fmaxf(v11, 0.f);
                }
                if (OUTM == 1) {
                    *(uint32_t*)(Chi + (size_t)rg0 * ldC + c)       = pack_h2(v00, v01);
                    *(uint32_t*)(Chi + (size_t)(rg0 + 8) * ldC + c) = pack_h2(v10, v11);
                } else {
                    // OUTM == 3 : fused final-layer scatter
                    #pragma unroll
                    for (int h = 0; h < 2; h++) {
                        const int rg = rg0 + h * 8;
                        const float va = (h == 0) ? v00 : v10;
                        const float vb = (h == 0) ? v01 : v11;
                        if (rg < BATCH) {
                            Cf[(size_t)rg * EMBED_DIM + c]     = va;
                            Cf[(size_t)rg * EMBED_DIM + c + 1] = vb;
                        } else {
                            float* p = Cf2 + (size_t)(rg - BATCH) * LATENT_DIM
                                     + STATE_DIM + c;
                            p[0] = va; p[1] = vb;
                        }
                    }
                }
            }
        }
    }
}

// ---------------------------------------------------------------------------
// One merged converter launch: X (hi/lo, + z_target cols 0:31 for x_next
// rows), W1/W2/W3/Wo (hi only). Weights -> [N][K] K-major.
// ---------------------------------------------------------------------------
#define XC   (ROWS_TOTAL * 32)
#define W1C  (512 * 32)
#define W2C  (512 * 512)
#define W3C  (512 * 512)
#define WOC  (128 * 512)
#define CONVTOT (XC + W1C + W2C + W3C + WOC)

__global__ void conv_all(const float* __restrict__ xk, const float* __restrict__ xn,
                         const float* __restrict__ W1, const float* __restrict__ W2,
                         const float* __restrict__ W3, const float* __restrict__ Wo,
                         __half* __restrict__ Xhi, __half* __restrict__ Xlo,
                         __half* __restrict__ W1thi,
                         __half* __restrict__ W2thi, __half* __restrict__ W3thi,
                         __half* __restrict__ Wothi,
                         float* __restrict__ zt)
{
    int i = blockIdx.x * 256 + threadIdx.x;
    if (i < XC) {
        int row = i >> 5, c = i & 31;
        float v;
        if (row < BATCH) {
            v = xk[row * 32 + c];
        } else {
            v = xn[(size_t)(row - BATCH) * 32 + c];
            // z_target[:, 0:32] = x_next
            zt[(size_t)(row - BATCH) * LATENT_DIM + c] = v;
        }
        __half h, l; split_h(v, h, l);
        size_t o = (size_t)row * 32 + c;
        Xhi[o] = h; Xlo[o] = l;
        return;
    }
    i -= XC;
    if (i < W1C) {                       // K=32, N=512, hi only (2-pass L1)
        int k = i / 512, n = i % 512;
        W1thi[n * 32 + k] = __float2half(W1[k * 512 + n]);
        return;
    }
    i -= W1C;
    if (i < W2C) {                       // K=512, N=512, hi only
        int k = i / 512, n = i % 512;
        W2thi[(size_t)n * 512 + k] = __float2half(W2[(size_t)k * 512 + n]);
        return;
    }
    i -= W2C;
    if (i < W3C) {
        int k = i / 512, n = i % 512;
        W3thi[(size_t)n * 512 + k] = __float2half(W3[(size_t)k * 512 + n]);
        return;
    }
    i -= W3C;
    {                                    // Wo: K=512, N=96, Npad=128, hi only
        int k = i / 128, n = i % 128;
        float v = (n < 96) ? Wo[(size_t)k * 96 + n] : 0.f;
        Wothi[(size_t)n * 512 + k] = __float2half(v);
    }
}

// ---------------------------------------------------------------------------
// Scan (unchanged, fp32-exact)
// ---------------------------------------------------------------------------
__device__ __forceinline__ float2 ffma2(float a, float2 b, float2 c) {
    float2 aa = make_float2(a, a);
    unsigned long long A = *reinterpret_cast<unsigned long long*>(&aa);
    unsigned long long B = *reinterpret_cast<unsigned long long*>(&b);
    unsigned long long C = *reinterpret_cast<unsigned long long*>(&c);
    asm("fma.rn.f32x2 %0, %1, %2, %0;" : "+l"(C) : "l"(A), "l"(B));
    return *reinterpret_cast<float2*>(&C);
}

#define SCAN_ROWS 8
__global__ __launch_bounds__(256)
void scan_kernel(const float* __restrict__ x_k, const float* __restrict__ u_seq,
                 const float* __restrict__ Amat, const float* __restrict__ Bmat,
                 const float* __restrict__ E,
                 float* __restrict__ z_pred, float* __restrict__ x_pred)
{
    __shared__ float zsh[SCAN_ROWS][LATENT_DIM];
    __shared__ float ush[SCAN_ROWS][CONTROL_DIM];

    const int tid = threadIdx.x;
    const int lr  = tid >> 5;
    const int j   = tid & 31;
    const int b   = blockIdx.x * SCAN_ROWS + lr;
    const int d0  = j * 4;

    float4 z;
    if (d0 < STATE_DIM) z = *(const float4*)(x_k + (size_t)b * STATE_DIM + d0);
    else                z = *(const float4*)(E   + (size_t)b * EMBED_DIM + (d0 - STATE_DIM));
    zsh[lr][d0 + 0] = z.x; zsh[lr][d0 + 1] = z.y;
    zsh[lr][d0 + 2] = z.z; zsh[lr][d0 + 3] = z.w;
    if (j < CONTROL_DIM)
        ush[lr][j] = u_seq[((size_t)b * MSEQ + 0) * CONTROL_DIM + j];
    __syncwarp();

    for (int i = 0; i < MSEQ; i++) {
        float2 acc01 = make_float2(0.f, 0.f);
        float2 acc23 = make_float2(0.f, 0.f);

        #pragma unroll
        for (int c = 0; c < CONTROL_DIM; c++) {
            const float uc = ush[lr][c];
            float4 brow = *(const float4*)(Bmat + (size_t)c * LATENT_DIM + d0);
            acc01 = ffma2(uc, make_float2(brow.x, brow.y), acc01);
            acc23 = ffma2(uc, make_float2(brow.z, brow.w), acc23);
        }
        #pragma unroll 32
        for (int k = 0; k < LATENT_DIM; k++) {
            const float zk = zsh[lr][k];
            float4 arow = *(const float4*)(Amat + (size_t)k * LATENT_DIM + d0);
            acc01 = ffma2(zk, make_float2(arow.x, arow.y), acc01);
            acc23 = ffma2(zk, make_float2(arow.z, arow.w), acc23);
        }
        __syncwarp();

        zsh[lr][d0 + 0] = acc01.x; zsh[lr][d0 + 1] = acc01.y;
        zsh[lr][d0 + 2] = acc23.x; zsh[lr][d0 + 3] = acc23.y;
        if (j < CONTROL_DIM && i + 1 < MSEQ)
            ush[lr][j] = u_seq[((size_t)b * MSEQ + (i + 1)) * CONTROL_DIM + j];

        const size_t orow = (size_t)b * MSEQ + i;
        float4 out = make_float4(acc01.x, acc01.y, acc23.x, acc23.y);
        *(float4*)(z_pred + orow * LATENT_DIM + d0) = out;
        if (d0 < STATE_DIM)
            *(float4*)(x_pred + orow * STATE_DIM + d0) = out;
        __syncwarp();
    }
}

// ---------------------------------------------------------------------------
// kernel_launch
// Inputs: 0:x_k 1:u_seq 2:x_next_seq 3:W1 4:b1 5:W2 6:b2 7:W3 8:b3
//         9:Wo 10:bo 11:A 12:Bmat
// ---------------------------------------------------------------------------
extern "C" void kernel_launch(void* const* d_in, const int* in_sizes, int n_in,
                              void* d_out, int out_size)
{
    const float* x_k    = (const float*)d_in[0];
    const float* u_seq  = (const float*)d_in[1];
    const float* x_next = (const float*)d_in[2];
    const float* W1     = (const float*)d_in[3];
    const float* b1     = (const float*)d_in[4];
    const float* W2     = (const float*)d_in[5];
    const float* b2     = (const float*)d_in[6];
    const float* W3     = (const float*)d_in[7];
    const float* b3     = (const float*)d_in[8];
    const float* Wo     = (const float*)d_in[9];
    const float* bo     = (const float*)d_in[10];
    const float* Amat   = (const float*)d_in[11];
    const float* Bmat   = (const float*)d_in[12];

    float* out      = (float*)d_out;
    float* z_pred   = out;
    float* x_pred   = out + (size_t)BATCH * MSEQ * LATENT_DIM;
    float* z_target = x_pred + (size_t)BATCH * MSEQ * STATE_DIM;

    __half *Xhi, *Xlo, *Hahi, *Hbhi;
    __half *W1thi, *W2thi, *W3thi, *Wothi;
    float* Exk;
    cudaGetSymbolAddress((void**)&Xhi,  g_Xhi);  cudaGetSymbolAddress((void**)&Xlo,  g_Xlo);
    cudaGetSymbolAddress((void**)&Hahi, g_Hahi);
    cudaGetSymbolAddress((void**)&Hbhi, g_Hbhi);
    cudaGetSymbolAddress((void**)&W1thi, g_W1thi);
    cudaGetSymbolAddress((void**)&W2thi, g_W2thi);
    cudaGetSymbolAddress((void**)&W3thi, g_W3thi);
    cudaGetSymbolAddress((void**)&Wothi, g_Wothi);
    cudaGetSymbolAddress((void**)&Exk, g_Exk);

    const int SMEM_P2 = 2 * 3 * TILE_B;   // 61440 (2-pass, 2 stages)
    const int SMEM_P1 = 4 * 2 * TILE_B;   // 81920 (1-pass, 4 stages)
    cudaFuncSetAttribute(gemm_mma<1,  2, 2, true,  1>,
                         cudaFuncAttributeMaxDynamicSharedMemorySize, SMEM_P2);
    cudaFuncSetAttribute(gemm_mma<16, 4, 1, true,  1>,
                         cudaFuncAttributeMaxDynamicSharedMemorySize, SMEM_P1);
    cudaFuncSetAttribute(gemm_mma<16, 4, 1, false, 3>,
                         cudaFuncAttributeMaxDynamicSharedMemorySize, SMEM_P1);

    // all conversions (+ z_target cols 0:31)                   (launch 1)
    conv_all<<<(CONVTOT + 255) / 256, 256>>>(
        x_k, x_next, W1, W2, W3, Wo,
        Xhi, Xlo, W1thi, W2thi, W3thi, Wothi, z_target);

    // L1: 2-pass (K=32), single-fp16 out -> Hahi               (launch 2)
    gemm_mma<1, 2, 2, true, 1><<<dim3(4, MTILES), 256, SMEM_P2>>>(
        Xhi, Xlo, 32, W1thi, 32, b1, Hahi, nullptr, nullptr, 512, 512);
    // L2: 1-pass fp16 -> Hbhi                                  (launch 3)
    gemm_mma<16, 4, 1, true, 1><<<dim3(4, MTILES), 256, SMEM_P1>>>(
        Hahi, nullptr, 512, W2thi, 512, b2, Hbhi, nullptr, nullptr, 512, 512);
    // L3: 1-pass fp16 -> Hahi                                  (launch 4)
    gemm_mma<16, 4, 1, true, 1><<<dim3(4, MTILES), 256, SMEM_P1>>>(
        Hbhi, nullptr, 512, W3thi, 512, b3, Hahi, nullptr, nullptr, 512, 512);
    // L4: 1-pass fp16, fused scatter -> Exk / z_target[32:128] (launch 5)
    gemm_mma<16, 4, 1, false, 3><<<dim3(1, MTILES), 256, SMEM_P1>>>(
        Hahi, nullptr, 512, Wothi, 512, bo, nullptr, Exk, z_target, 96, 96);

    // scan                                                     (launch 6)
    scan_kernel<<<BATCH / SCAN_ROWS, 256>>>(x_k, u_seq, Amat, Bmat, Exk,
                                            z_pred, x_pred);

    (void)in_sizes; (void)n_in; (void)out_size;
}

// round 16
// speedup vs baseline: 1.9322x; 1.0050x over previous
#include <cuda_runtime.h>
#include <cuda_fp16.h>
#include <cstdint>

// ---------------------------------------------------------------------------
// Problem constants
// ---------------------------------------------------------------------------
#define BATCH      2048
#define MSEQ       64
#define STATE_DIM  32
#define CONTROL_DIM 8
#define EMBED_DIM  96
#define LATENT_DIM 128
#define HIDDEN     512
#define ROWS_XNEXT (BATCH * MSEQ)            // 131072
#define ROWS_TOTAL (BATCH + ROWS_XNEXT)      // 133120
#define MTILES     (ROWS_TOTAL / 128)        // 1040

// ---------------------------------------------------------------------------
// Scratch (__device__ globals; no allocs allowed)
// ---------------------------------------------------------------------------
__device__ __half g_Xhi[(size_t)ROWS_TOTAL * 32];
__device__ __half g_Xlo[(size_t)ROWS_TOTAL * 32];
__device__ __half g_Hahi[(size_t)ROWS_TOTAL * HIDDEN];   // H1 / H3 (single fp16)
__device__ __half g_Hbhi[(size_t)ROWS_TOTAL * HIDDEN];   // H2 (single fp16)
__device__ float  g_Exk[(size_t)BATCH * EMBED_DIM];      // encoder(x_k) only
__device__ __half g_W1thi[512 * 32];                     // [N][K], hi only (2-pass)
__device__ __half g_W2thi[512 * 512];
__device__ __half g_W3thi[512 * 512];
__device__ __half g_Wothi[128 * 512];                    // padded N 96->128

// ---------------------------------------------------------------------------
// Helpers
// ---------------------------------------------------------------------------
__device__ __forceinline__ uint32_t smem_u32(const void* p) {
    uint32_t a;
    asm("{ .reg .u64 t; cvta.to.shared.u64 t, %1; cvt.u32.u64 %0, t; }"
        : "=r"(a) : "l"(p));
    return a;
}

#define CP16(dst, src) \
    asm volatile("cp.async.cg.shared.global [%0], [%1], 16;" \
                 :: "r"(dst), "l"(src))
#define CP_COMMIT() asm volatile("cp.async.commit_group;")
#define CP_WAIT(n)  asm volatile("cp.async.wait_group %0;" :: "n"(n))

__device__ __forceinline__ void ldsm4(uint32_t* d, uint32_t addr) {
    asm volatile("ldmatrix.sync.aligned.m8n8.x4.shared.b16 {%0,%1,%2,%3}, [%4];"
                 : "=r"(d[0]), "=r"(d[1]), "=r"(d[2]), "=r"(d[3]) : "r"(addr));
}
__device__ __forceinline__ void mma16816(float* c, const uint32_t* a,
                                         uint32_t b0, uint32_t b1) {
    asm volatile(
        "mma.sync.aligned.m16n8k16.row.col.f32.f16.f16.f32 "
        "{%0,%1,%2,%3}, {%4,%5,%6,%7}, {%8,%9}, {%0,%1,%2,%3};"
        : "+f"(c[0]), "+f"(c[1]), "+f"(c[2]), "+f"(c[3])
        : "r"(a[0]), "r"(a[1]), "r"(a[2]), "r"(a[3]), "r"(b0), "r"(b1));
}

__device__ __forceinline__ void split_h(float v, __half& h, __half& l) {
    h = __float2half(v);
    l = __float2half(v - __half2float(h));
}
__device__ __forceinline__ uint32_t pack_h2(float a, float b) {
    __half2 h = __floats2half2_rn(a, b);
    return *reinterpret_cast<uint32_t*>(&h);
}

// ---------------------------------------------------------------------------
// fp16 mma.sync GEMM, NPASS-split, fp32 accumulate. (PROVEN config)
// Block 128x128, 8 warps, warp tile 64x32, 2 blocks/SM.
// NPASS==2: C = (Ah+Al)*Bh   NPASS==1: C = Ah*Bh
// OUTM: 1 = single fp16 store
//       3 = fused final-layer store: rows<BATCH -> Exk[96-wide],
//           rows>=BATCH -> z_target[(r-BATCH)*128 + 32 + c] (c<96 guard)
// ---------------------------------------------------------------------------
#define TILE_B  10240          // 128 rows * 80 bytes

template<int KB, int STAGES, int NPASS, bool RELU, int OUTM>
__global__ __launch_bounds__(256, 2)
void gemm_mma(const __half* __restrict__ Ahi, const __half* __restrict__ Alo,
              int ldA,
              const __half* __restrict__ Bhi,
              int ldB,
              const float* __restrict__ bias,
              __half* __restrict__ Chi,
              float* __restrict__ Cf, float* __restrict__ Cf2,
              int ldC, int Nlim)
{
    constexpr int A_TILES = (NPASS == 1) ? 1 : 2;
    constexpr int STG     = (A_TILES + 1) * TILE_B;
    constexpr uint32_t BOFF = A_TILES * TILE_B;            // Bh tile

    extern __shared__ __align__(128) uint8_t dsm[];
    const uint32_t sbase = smem_u32(dsm);

    const int tid  = threadIdx.x;
    const int wid  = tid >> 5;
    const int lane = tid & 31;
    const int row0 = blockIdx.y * 128;
    const int n0   = blockIdx.x * 128;

    const int m_base = (wid >> 2) * 64;   // 0 or 64
    const int n_base = (wid & 3) * 32;    // 0,32,64,96

    const uint32_t aoff = (uint32_t)(m_base + (lane & 15)) * 80 + ((lane >> 4) << 4);
    const uint32_t boff = (uint32_t)(n_base + (lane & 15)) * 80 + ((lane >> 4) << 4);

    float acc[4][4][4];
    #pragma unroll
    for (int f = 0; f < 4; f++)
        #pragma unroll
        for (int g = 0; g < 4; g++)
            #pragma unroll
            for (int e = 0; e < 4; e++)
                acc[f][g][e] = 0.f;

    auto load_kb = [&](int kb, int st) {
        const uint32_t sa = sbase + st * STG;
        #pragma unroll
        for (int t = 0; t < 2; t++) {
            int q = tid + t * 256;       // 0..511
            int r = q >> 2, c = q & 3;
            uint32_t so = (uint32_t)r * 80 + c * 16;
            size_t ga = (size_t)(row0 + r) * ldA + kb * 32 + c * 8;
            size_t gb = (size_t)(n0 + r) * ldB + kb * 32 + c * 8;
            CP16(sa + so, Ahi + ga);
            if (NPASS > 1) CP16(sa + TILE_B + so, Alo + ga);
            CP16(sa + BOFF + so, Bhi + gb);
        }
    };

    auto compute_st = [&](int st) {
        const uint32_t sa = sbase + st * STG;
        #pragma unroll
        for (int ks = 0; ks < 2; ks++) {
            uint32_t ah[4][4], bh[2][4];
            #pragma unroll
            for (int f = 0; f < 4; f++)
                ldsm4(ah[f], sa + aoff + f * (16 * 80) + ks * 32);
            #pragma unroll
            for (int p = 0; p < 2; p++)
                ldsm4(bh[p], sa + BOFF + boff + p * (16 * 80) + ks * 32);
            // pass 1: Ah*Bh
            #pragma unroll
            for (int f = 0; f < 4; f++)
                #pragma unroll
                for (int g = 0; g < 4; g++) {
                    const int p = g >> 1, s = g & 1;
                    mma16816(acc[f][g], ah[f], bh[p][s], bh[p][s + 2]);
                }
            // pass 2 (NPASS>1): Al*Bh
            if (NPASS > 1) {
                uint32_t al[4][4];
                #pragma unroll
                for (int f = 0; f < 4; f++)
                    ldsm4(al[f], sa + TILE_B + aoff + f * (16 * 80) + ks * 32);
                #pragma unroll
                for (int f = 0; f < 4; f++)
                    #pragma unroll
                    for (int g = 0; g < 4; g++) {
                        const int p = g >> 1, s = g & 1;
                        mma16816(acc[f][g], al[f], bh[p][s], bh[p][s + 2]);
                    }
            }
        }
    };

    // prologue
    #pragma unroll
    for (int s = 0; s < STAGES - 1; s++) {
        if (s < KB) load_kb(s, s);
        CP_COMMIT();
    }
    // mainloop
    for (int kb = 0; kb < KB; kb++) {
        CP_WAIT(STAGES - 2);
        __syncthreads();
        const int nkb = kb + STAGES - 1;
        if (nkb < KB) load_kb(nkb, nkb % STAGES);
        CP_COMMIT();
        compute_st(kb % STAGES);
    }

    // epilogue
    #pragma unroll
    for (int f = 0; f < 4; f++) {
        const int rg0 = row0 + m_base + f * 16 + (lane >> 2);
        #pragma unroll
        for (int g = 0; g < 4; g++) {
            const int c = n0 + n_base + g * 8 + (lane & 3) * 2;
            if (c < Nlim) {
                const float b0 = bias[c], b1 = bias[c + 1];
                float v00 = acc[f][g][0] + b0, v01 = acc[f][g][1] + b1;
                float v10 = acc[f][g][2] + b0, v11 = acc[f][g][3] + b1;
                if (RELU) {
                    v00 = fmaxf(v00, 0.f); v01 = fmaxf(v01, 0.f);
                    v10 = fmaxf(v10, 0.f); v11 = fmaxf(v11, 0.f);
                }
                if (OUTM == 1) {
                    *(uint32_t*)(Chi + (size_t)rg0 * ldC + c)       = pack_h2(v00, v01);
                    *(uint32_t*)(Chi + (size_t)(rg0 + 8) * ldC + c) = pack_h2(v10, v11);
                } else {
                    // OUTM == 3 : fused final-layer scatter
                    #pragma unroll
                    for (int h = 0; h < 2; h++) {
                        const int rg = rg0 + h * 8;
                        const float va = (h == 0) ? v00 : v10;
                        const float vb = (h == 0) ? v01 : v11;
                        if (rg < BATCH) {
                            Cf[(size_t)rg * EMBED_DIM + c]     = va;
                            Cf[(size_t)rg * EMBED_DIM + c + 1] = vb;
                        } else {
                            float* p = Cf2 + (size_t)(rg - BATCH) * LATENT_DIM
                                     + STATE_DIM + c;
                            p[0] = va; p[1] = vb;
                        }
                    }
                }
            }
        }
    }
}

// ---------------------------------------------------------------------------
// One merged converter launch: X (hi/lo, + z_target cols 0:31 for x_next
// rows), W1/W2/W3/Wo (hi only). Weights -> [N][K] K-major.
// ---------------------------------------------------------------------------
#define XC   (ROWS_TOTAL * 32)
#define W1C  (512 * 32)
#define W2C  (512 * 512)
#define W3C  (512 * 512)
#define WOC  (128 * 512)
#define CONVTOT (XC + W1C + W2C + W3C + WOC)

__global__ void conv_all(const float* __restrict__ xk, const float* __restrict__ xn,
                         const float* __restrict__ W1, const float* __restrict__ W2,
                         const float* __restrict__ W3, const float* __restrict__ Wo,
                         __half* __restrict__ Xhi, __half* __restrict__ Xlo,
                         __half* __restrict__ W1thi,
                         __half* __restrict__ W2thi, __half* __restrict__ W3thi,
                         __half* __restrict__ Wothi,
                         float* __restrict__ zt)
{
    int i = blockIdx.x * 256 + threadIdx.x;
    if (i < XC) {
        int row = i >> 5, c = i & 31;
        float v;
        if (row < BATCH) {
            v = xk[row * 32 + c];
        } else {
            v = xn[(size_t)(row - BATCH) * 32 + c];
            zt[(size_t)(row - BATCH) * LATENT_DIM + c] = v;   // z_target[:,0:32]
        }
        __half h, l; split_h(v, h, l);
        size_t o = (size_t)row * 32 + c;
        Xhi[o] = h; Xlo[o] = l;
        return;
    }
    i -= XC;
    if (i < W1C) {                       // K=32, N=512, hi only (2-pass L1)
        int k = i / 512, n = i % 512;
        W1thi[n * 32 + k] = __float2half(W1[k * 512 + n]);
        return;
    }
    i -= W1C;
    if (i < W2C) {                       // K=512, N=512, hi only
        int k = i / 512, n = i % 512;
        W2thi[(size_t)n * 512 + k] = __float2half(W2[(size_t)k * 512 + n]);
        return;
    }
    i -= W2C;
    if (i < W3C) {
        int k = i / 512, n = i % 512;
        W3thi[(size_t)n * 512 + k] = __float2half(W3[(size_t)k * 512 + n]);
        return;
    }
    i -= W3C;
    {                                    // Wo: K=512, N=96, Npad=128, hi only
        int k = i / 128, n = i % 128;
        float v = (n < 96) ? Wo[(size_t)k * 96 + n] : 0.f;
        Wothi[(size_t)n * 512 + k] = __float2half(v);
    }
}

// ---------------------------------------------------------------------------
// Scan, row-shared: 128 blocks x 128 threads; warp owns 4 batch rows.
// Lane j: row = 4*wid + (j>>3), dims { 4*(j&7) + 32q + 0..3, q=0..3 }.
// A (64KB) + Bmat staged in smem once. zsh rows padded to 132 floats:
// multiple of 4 (float4-ALIGNED — stride 129 trapped with misaligned
// address) and 132 mod 32 = 4 banks -> the 4 rloc-groups per warp sit at
// bank offsets 0/4/8/12; LDS.128 phases (8 lanes each) are contiguous
// 128B -> conflict-free; scalar zsh broadcasts hit 4 distinct banks.
// Per-dim accumulation order identical to the R14 scan (bitwise same).
// ---------------------------------------------------------------------------
#define ZPAD 132
#define SC_SMEM ((128 * 128 + 8 * 128 + 16 * ZPAD + 16 * 8) * 4)   // 78592 B

__global__ __launch_bounds__(128, 1)
void scan_kernel(const float* __restrict__ x_k, const float* __restrict__ u_seq,
                 const float* __restrict__ Amat, const float* __restrict__ Bmat,
                 const float* __restrict__ E,
                 float* __restrict__ z_pred, float* __restrict__ x_pred)
{
    extern __shared__ float sm[];
    float* Asm = sm;                         // [128][128]
    float* Bsm = Asm + 128 * 128;            // [8][128]
    float* zsh = Bsm + 8 * 128;              // [16][ZPAD]
    float* ush = zsh + 16 * ZPAD;            // [16][8]

    const int tid  = threadIdx.x;
    const int wid  = tid >> 5;
    const int j    = tid & 31;
    const int rloc = wid * 4 + (j >> 3);     // block row 0..15
    const int b    = blockIdx.x * 16 + rloc;
    const int cbase = (j & 7) * 4;           // 0,4,...,28

    // stage A (16384 floats = 4096 float4, 32 per thread)
    #pragma unroll
    for (int i = 0; i < 32; i++) {
        int idx = tid + i * 128;
        int row = idx >> 5, c4 = idx & 31;
        *(float4*)&Asm[row * 128 + c4 * 4] = ((const float4*)Amat)[idx];
    }
    // stage B (256 float4, 2 per thread)
    #pragma unroll
    for (int i = 0; i < 2; i++) {
        int idx = tid + i * 128;
        ((float4*)Bsm)[idx] = ((const float4*)Bmat)[idx];
    }
    // init z = [x_k | Exk]
    {
        float4 v0 = *(const float4*)(x_k + (size_t)b * STATE_DIM + cbase);
        *(float4*)&zsh[rloc * ZPAD + cbase] = v0;
        #pragma unroll
        for (int q = 1; q < 4; q++) {
            float4 v = *(const float4*)(E + (size_t)b * EMBED_DIM + cbase + 32 * q - 32);
            *(float4*)&zsh[rloc * ZPAD + cbase + 32 * q] = v;
        }
    }
    // init u (thread t -> row t>>3, ctrl t&7; warp-local ownership)
    ush[(tid >> 3) * 8 + (tid & 7)] =
        u_seq[((size_t)(blockIdx.x * 16 + (tid >> 3)) * MSEQ + 0) * CONTROL_DIM + (tid & 7)];
    __syncthreads();

    for (int i = 0; i < MSEQ; i++) {
        float2 acc[4][2];
        #pragma unroll
        for (int q = 0; q < 4; q++) {
            acc[q][0] = make_float2(0.f, 0.f);
            acc[q][1] = make_float2(0.f, 0.f);
        }
        // u @ Bmat
        #pragma unroll
        for (int c = 0; c < CONTROL_DIM; c++) {
            const float uc = ush[rloc * 8 + c];
            #pragma unroll
            for (int q = 0; q < 4; q++) {
                float4 br = *(float4*)&Bsm[c * 128 + cbase + 32 * q];
                float2 aa = make_float2(uc, uc);
                unsigned long long A0 = *(unsigned long long*)&aa;
                unsigned long long B0, C0;
                float2 t0 = make_float2(br.x, br.y);
                B0 = *(unsigned long long*)&t0; C0 = *(unsigned long long*)&acc[q][0];
                asm("fma.rn.f32x2 %0, %1, %2, %0;" : "+l"(C0) : "l"(A0), "l"(B0));
                acc[q][0] = *(float2*)&C0;
                float2 t1 = make_float2(br.z, br.w);
                B0 = *(unsigned long long*)&t1; C0 = *(unsigned long long*)&acc[q][1];
                asm("fma.rn.f32x2 %0, %1, %2, %0;" : "+l"(C0) : "l"(A0), "l"(B0));
                acc[q][1] = *(float2*)&C0;
            }
        }
        // z @ A
        #pragma unroll 4
        for (int k = 0; k < LATENT_DIM; k++) {
            const float zk = zsh[rloc * ZPAD + k];
            float2 aa = make_float2(zk, zk);
            unsigned long long A0 = *(unsigned long long*)&aa;
            #pragma unroll
            for (int q = 0; q < 4; q++) {
                float4 ar = *(float4*)&Asm[k * 128 + cbase + 32 * q];
                unsigned long long B0, C0;
                float2 t0 = make_float2(ar.x, ar.y);
                B0 = *(unsigned long long*)&t0; C0 = *(unsigned long long*)&acc[q][0];
                asm("fma.rn.f32x2 %0, %1, %2, %0;" : "+l"(C0) : "l"(A0), "l"(B0));
                acc[q][0] = *(float2*)&C0;
                float2 t1 = make_float2(ar.z, ar.w);
                B0 = *(unsigned long long*)&t1; C0 = *(unsigned long long*)&acc[q][1];
                asm("fma.rn.f32x2 %0, %1, %2, %0;" : "+l"(C0) : "l"(A0), "l"(B0));
                acc[q][1] = *(float2*)&C0;
            }
        }
        __syncwarp();   // all zsh/ush reads done before overwrite

        const size_t orow = (size_t)b * MSEQ + i;
        #pragma unroll
        for (int q = 0; q < 4; q++) {
            float4 v = make_float4(acc[q][0].x, acc[q][0].y, acc[q][1].x, acc[q][1].y);
            *(float4*)&zsh[rloc * ZPAD + cbase + 32 * q] = v;
            *(float4*)(z_pred + orow * LATENT_DIM + cbase + 32 * q) = v;
            if (q == 0)
                *(float4*)(x_pred + orow * STATE_DIM + cbase) = v;
        }
        if (i + 1 < MSEQ)
            ush[(tid >> 3) * 8 + (tid & 7)] =
                u_seq[((size_t)(blockIdx.x * 16 + (tid >> 3)) * MSEQ + i + 1) * CONTROL_DIM
                      + (tid & 7)];
        __syncwarp();   // new z/u visible before next iter's reads
    }
}

// ---------------------------------------------------------------------------
// kernel_launch
// Inputs: 0:x_k 1:u_seq 2:x_next_seq 3:W1 4:b1 5:W2 6:b2 7:W3 8:b3
//         9:Wo 10:bo 11:A 12:Bmat
// ---------------------------------------------------------------------------
extern "C" void kernel_launch(void* const* d_in, const int* in_sizes, int n_in,
                              void* d_out, int out_size)
{
    const float* x_k    = (const float*)d_in[0];
    const float* u_seq  = (const float*)d_in[1];
    const float* x_next = (const float*)d_in[2];
    const float* W1     = (const float*)d_in[3];
    const float* b1     = (const float*)d_in[4];
    const float* W2     = (const float*)d_in[5];
    const float* b2     = (const float*)d_in[6];
    const float* W3     = (const float*)d_in[7];
    const float* b3     = (const float*)d_in[8];
    const float* Wo     = (const float*)d_in[9];
    const float* bo     = (const float*)d_in[10];
    const float* Amat   = (const float*)d_in[11];
    const float* Bmat   = (const float*)d_in[12];

    float* out      = (float*)d_out;
    float* z_pred   = out;
    float* x_pred   = out + (size_t)BATCH * MSEQ * LATENT_DIM;
    float* z_target = x_pred + (size_t)BATCH * MSEQ * STATE_DIM;

    __half *Xhi, *Xlo, *Hahi, *Hbhi;
    __half *W1thi, *W2thi, *W3thi, *Wothi;
    float* Exk;
    cudaGetSymbolAddress((void**)&Xhi,  g_Xhi);  cudaGetSymbolAddress((void**)&Xlo,  g_Xlo);
    cudaGetSymbolAddress((void**)&Hahi, g_Hahi);
    cudaGetSymbolAddress((void**)&Hbhi, g_Hbhi);
    cudaGetSymbolAddress((void**)&W1thi, g_W1thi);
    cudaGetSymbolAddress((void**)&W2thi, g_W2thi);
    cudaGetSymbolAddress((void**)&W3thi, g_W3thi);
    cudaGetSymbolAddress((void**)&Wothi, g_Wothi);
    cudaGetSymbolAddress((void**)&Exk, g_Exk);

    const int SMEM_P2 = 2 * 3 * TILE_B;   // 61440 (2-pass, 2 stages)
    const int SMEM_P1 = 4 * 2 * TILE_B;   // 81920 (1-pass, 4 stages)
    cudaFuncSetAttribute(gemm_mma<1,  2, 2, true,  1>,
                         cudaFuncAttributeMaxDynamicSharedMemorySize, SMEM_P2);
    cudaFuncSetAttribute(gemm_mma<16, 4, 1, true,  1>,
                         cudaFuncAttributeMaxDynamicSharedMemorySize, SMEM_P1);
    cudaFuncSetAttribute(gemm_mma<16, 4, 1, false, 3>,
                         cudaFuncAttributeMaxDynamicSharedMemorySize, SMEM_P1);
    cudaFuncSetAttribute(scan_kernel,
                         cudaFuncAttributeMaxDynamicSharedMemorySize, SC_SMEM);

    // all conversions (+ z_target cols 0:31)                   (launch 1)
    conv_all<<<(CONVTOT + 255) / 256, 256>>>(
        x_k, x_next, W1, W2, W3, Wo,
        Xhi, Xlo, W1thi, W2thi, W3thi, Wothi, z_target);

    // L1: 2-pass (K=32), single-fp16 out -> Hahi               (launch 2)
    gemm_mma<1, 2, 2, true, 1><<<dim3(4, MTILES), 256, SMEM_P2>>>(
        Xhi, Xlo, 32, W1thi, 32, b1, Hahi, nullptr, nullptr, 512, 512);
    // L2: 1-pass fp16 -> Hbhi                                  (launch 3)
    gemm_mma<16, 4, 1, true, 1><<<dim3(4, MTILES), 256, SMEM_P1>>>(
        Hahi, nullptr, 512, W2thi, 512, b2, Hbhi, nullptr, nullptr, 512, 512);
    // L3: 1-pass fp16 -> Hahi                                  (launch 4)
    gemm_mma<16, 4, 1, true, 1><<<dim3(4, MTILES), 256, SMEM_P1>>>(
        Hbhi, nullptr, 512, W3thi, 512, b3, Hahi, nullptr, nullptr, 512, 512);
    // L4: 1-pass fp16, fused scatter -> Exk / z_target[32:128] (launch 5)
    gemm_mma<16, 4, 1, false, 3><<<dim3(1, MTILES), 256, SMEM_P1>>>(
        Hahi, nullptr, 512, Wothi, 512, bo, nullptr, Exk, z_target, 96, 96);

    // scan (row-shared, smem-resident A)                       (launch 6)
    scan_kernel<<<BATCH / 16, 128, SC_SMEM>>>(x_k, u_seq, Amat, Bmat, Exk,
                                              z_pred, x_pred);

    (void)in_sizes; (void)n_in; (void)out_size;
}